// round 1
// baseline (speedup 1.0000x reference)
#include <cuda_runtime.h>
#include <math.h>

#define BB 4
#define NN 4096
#define CC 1024
#define HH 16
#define DD 64
#define MTOT (BB*NN)        // 16384
#define QKVC (3*CC)         // 3072

// Scratch (allocation-free: device globals)
__device__ float g_qkv[(size_t)MTOT * QKVC];   // [16384, 3072] post-elu q,k + raw v
__device__ float g_attn[(size_t)MTOT * CC];    // [16384, 1024] attention out (pre-proj)
__device__ float g_kv[BB*HH*DD*DD];            // [64, 64, 64] per-head state
__device__ float g_ksum[BB*HH*DD];             // [64, 64]

// ---------------------------------------------------------------------------
// Tiled fp32 SGEMM: C = A[M,K] @ B[K,N]  (+ optional elu+1 / bias epilogue)
// BM=BN=128, BK=8, 256 threads, 8x8 per thread.
// Assumes M%128==0, N%128==0, K%8==0 (true for both GEMMs here).
// ---------------------------------------------------------------------------
template<bool ELU, bool BIAS>
__global__ __launch_bounds__(256) void sgemm_kernel(
    const float* __restrict__ A, const float* __restrict__ B,
    const float* __restrict__ bias, float* __restrict__ C,
    int M, int N, int K)
{
    __shared__ float As[8][128];
    __shared__ float Bs[8][128];

    const int tid = threadIdx.x;
    const int tx = tid & 15;       // 0..15 (N dir)
    const int ty = tid >> 4;       // 0..15 (M dir)

    const int arow = tid >> 1;             // 0..127
    const int acol = (tid & 1) * 4;        // 0 or 4
    const int brow = tid >> 5;             // 0..7
    const int bcol = (tid & 31) * 4;       // 0..124

    const float* Ap = A + (size_t)(blockIdx.y * 128 + arow) * K + acol;
    const float* Bp = B + (size_t)brow * N + blockIdx.x * 128 + bcol;

    float acc[8][8];
    #pragma unroll
    for (int i = 0; i < 8; i++)
        #pragma unroll
        for (int j = 0; j < 8; j++) acc[i][j] = 0.f;

    for (int k0 = 0; k0 < K; k0 += 8) {
        float4 a4 = *(const float4*)Ap;  Ap += 8;
        float4 b4 = *(const float4*)Bp;  Bp += (size_t)8 * N;

        As[acol + 0][arow] = a4.x;
        As[acol + 1][arow] = a4.y;
        As[acol + 2][arow] = a4.z;
        As[acol + 3][arow] = a4.w;
        *(float4*)&Bs[brow][bcol] = b4;
        __syncthreads();

        #pragma unroll
        for (int kk = 0; kk < 8; kk++) {
            float ar[8], br[8];
            *(float4*)&ar[0] = *(const float4*)&As[kk][ty * 4];
            *(float4*)&ar[4] = *(const float4*)&As[kk][64 + ty * 4];
            *(float4*)&br[0] = *(const float4*)&Bs[kk][tx * 4];
            *(float4*)&br[4] = *(const float4*)&Bs[kk][64 + tx * 4];
            #pragma unroll
            for (int i = 0; i < 8; i++)
                #pragma unroll
                for (int j = 0; j < 8; j++)
                    acc[i][j] += ar[i] * br[j];
        }
        __syncthreads();
    }

    #pragma unroll
    for (int i = 0; i < 8; i++) {
        int m = blockIdx.y * 128 + ((i < 4) ? (ty * 4 + i) : (64 + ty * 4 + i - 4));
        #pragma unroll
        for (int j = 0; j < 8; j++) {
            int n = blockIdx.x * 128 + ((j < 4) ? (tx * 4 + j) : (64 + tx * 4 + j - 4));
            float v = acc[i][j];
            if (ELU) {
                // elu(x)+1 = x+1 (x>0) else exp(x); only q,k columns (< 2048)
                if (n < 2048) v = (v > 0.f) ? (v + 1.f) : expf(v);
            }
            if (BIAS) v += bias[n];
            C[(size_t)m * N + n] = v;
        }
    }
}

// ---------------------------------------------------------------------------
// Per-(b,h) KV state: kv[d][e] = sum_n k[n,d]*v[n,e]; ksum[d] = sum_n k[n,d]
// 64 blocks (one per b,h), 256 threads (16x16, 4x4 per thread), K chunks of 32.
// ---------------------------------------------------------------------------
__global__ __launch_bounds__(256) void kv_kernel(
    const float* __restrict__ qkv, float* __restrict__ kvout,
    float* __restrict__ ksum)
{
    const int bh = blockIdx.x;           // 0..63
    const int b = bh >> 4, h = bh & 15;
    const float* kbase = qkv + (size_t)b * NN * QKVC + CC + h * DD;
    const float* vbase = qkv + (size_t)b * NN * QKVC + 2 * CC + h * DD;

    __shared__ float ks[32][64];
    __shared__ float vs[32][64];

    const int tid = threadIdx.x;
    const int e0 = (tid & 15) * 4;
    const int d0 = (tid >> 4) * 4;

    float acc[4][4];
    #pragma unroll
    for (int i = 0; i < 4; i++)
        #pragma unroll
        for (int j = 0; j < 4; j++) acc[i][j] = 0.f;
    float ksacc = 0.f;

    for (int n0 = 0; n0 < NN; n0 += 32) {
        #pragma unroll
        for (int it = 0; it < 2; it++) {
            int idx = tid + it * 256;            // 0..511
            int r = idx >> 4, c = (idx & 15) * 4;
            *(float4*)&ks[r][c] = *(const float4*)(kbase + (size_t)(n0 + r) * QKVC + c);
            *(float4*)&vs[r][c] = *(const float4*)(vbase + (size_t)(n0 + r) * QKVC + c);
        }
        __syncthreads();
        #pragma unroll 8
        for (int nn = 0; nn < 32; nn++) {
            float kd[4], ve[4];
            *(float4*)kd = *(const float4*)&ks[nn][d0];
            *(float4*)ve = *(const float4*)&vs[nn][e0];
            #pragma unroll
            for (int i = 0; i < 4; i++)
                #pragma unroll
                for (int j = 0; j < 4; j++)
                    acc[i][j] += kd[i] * ve[j];
            if (tid < 64) ksacc += ks[nn][tid];
        }
        __syncthreads();
    }

    float* kvo = kvout + (size_t)bh * DD * DD;
    #pragma unroll
    for (int i = 0; i < 4; i++)
        #pragma unroll
        for (int j = 0; j < 4; j++)
            kvo[(d0 + i) * DD + e0 + j] = acc[i][j];
    if (tid < 64) ksum[bh * DD + tid] = ksacc;
}

// ---------------------------------------------------------------------------
// out[b,n,h,e] = (sum_d q[n,d]*kv[d,e]) / (sum_d q[n,d]*ksum[d] + 1e-6)
// grid (NN/64, B*H); 256 threads: 64 rows x 4 col-chunks of 16.
// Writes directly into [B,N,C] layout for the projection GEMM.
// ---------------------------------------------------------------------------
__global__ __launch_bounds__(256) void qout_kernel(
    const float* __restrict__ qkv, const float* __restrict__ kvmat,
    const float* __restrict__ ksum, float* __restrict__ attn)
{
    const int bh = blockIdx.y;
    const int b = bh >> 4, h = bh & 15;
    const int n0 = blockIdx.x * 64;

    __shared__ float kvs[64][64];
    __shared__ float qs[64][64];
    __shared__ float kss[64];

    const int tid = threadIdx.x;
    const float* qbase = qkv + (size_t)b * NN * QKVC + h * DD;
    const float* kvb = kvmat + (size_t)bh * DD * DD;

    #pragma unroll
    for (int it = 0; it < 4; it++) {
        int idx = tid + it * 256;            // 0..1023 (float4 units)
        int r = idx >> 4, c = (idx & 15) * 4;
        *(float4*)&kvs[r][c] = *(const float4*)(kvb + r * DD + c);
        *(float4*)&qs[r][c]  = *(const float4*)(qbase + (size_t)(n0 + r) * QKVC + c);
    }
    if (tid < 64) kss[tid] = ksum[bh * DD + tid];
    __syncthreads();

    const int r = tid >> 2;            // row 0..63
    const int e0 = (tid & 3) * 16;     // col chunk

    float acc[16];
    #pragma unroll
    for (int j = 0; j < 16; j++) acc[j] = 0.f;
    float zden = 0.f;

    #pragma unroll
    for (int d = 0; d < 64; d++) {
        float qd = qs[r][d];
        zden += qd * kss[d];
        #pragma unroll
        for (int j = 0; j < 16; j++)
            acc[j] += qd * kvs[d][e0 + j];
    }
    float z = 1.f / (zden + 1e-6f);

    float* out = attn + ((size_t)b * NN + n0 + r) * CC + h * DD + e0;
    #pragma unroll
    for (int j = 0; j < 16; j += 4) {
        float4 v = make_float4(acc[j] * z, acc[j + 1] * z, acc[j + 2] * z, acc[j + 3] * z);
        *(float4*)(out + j) = v;
    }
}

// ---------------------------------------------------------------------------
extern "C" void kernel_launch(void* const* d_in, const int* in_sizes, int n_in,
                              void* d_out, int out_size)
{
    const float* x     = (const float*)d_in[0];
    const float* Wqkv  = (const float*)d_in[1];
    const float* Wproj = (const float*)d_in[2];
    const float* bproj = (const float*)d_in[3];
    float* out = (float*)d_out;

    float *qkv_p, *attn_p, *kv_p, *ksum_p;
    cudaGetSymbolAddress((void**)&qkv_p,  g_qkv);
    cudaGetSymbolAddress((void**)&attn_p, g_attn);
    cudaGetSymbolAddress((void**)&kv_p,   g_kv);
    cudaGetSymbolAddress((void**)&ksum_p, g_ksum);

    // 1) qkv = x @ W_qkv, fused elu+1 on q,k columns
    sgemm_kernel<true, false><<<dim3(QKVC / 128, MTOT / 128), 256>>>(
        x, Wqkv, nullptr, qkv_p, MTOT, QKVC, CC);

    // 2) per-(b,h) KV state + ksum
    kv_kernel<<<BB * HH, 256>>>(qkv_p, kv_p, ksum_p);

    // 3) q @ KV with normalizer, write [B,N,C]
    qout_kernel<<<dim3(NN / 64, BB * HH), 256>>>(qkv_p, kv_p, ksum_p, attn_p);

    // 4) final = attn @ W_proj + b_proj
    sgemm_kernel<false, true><<<dim3(CC / 128, MTOT / 128), 256>>>(
        attn_p, Wproj, bproj, out, MTOT, CC, CC);
}

// round 3
// speedup vs baseline: 1.9447x; 1.9447x over previous
#include <cuda_runtime.h>
#include <cuda_bf16.h>
#include <math.h>
#include <cstdint>

#define BB 4
#define NN 4096
#define CC 1024
#define HH 16
#define DD 64
#define MTOT (BB*NN)        // 16384
#define QKVC (3*CC)         // 3072
#define KDIM 1024

// ---------------- scratch (device globals; allocation-free) ----------------
__device__ float g_qkv[(size_t)MTOT * QKVC];              // fp32 qkv (post-elu q,k)
__device__ __nv_bfloat16 g_xhi[(size_t)MTOT * CC];
__device__ __nv_bfloat16 g_xlo[(size_t)MTOT * CC];
__device__ __nv_bfloat16 g_attn_hi[(size_t)MTOT * CC];
__device__ __nv_bfloat16 g_attn_lo[(size_t)MTOT * CC];
__device__ __nv_bfloat16 g_wqkvT_hi[(size_t)QKVC * KDIM]; // [3072][1024] (N-major)
__device__ __nv_bfloat16 g_wqkvT_lo[(size_t)QKVC * KDIM];
__device__ __nv_bfloat16 g_wprojT_hi[(size_t)CC * KDIM];  // [1024][1024]
__device__ __nv_bfloat16 g_wprojT_lo[(size_t)CC * KDIM];
__device__ float g_kv[BB*HH*DD*DD];
__device__ float g_ksum[BB*HH*DD];

// ---------------- PTX helpers (all baseline sm_80-class — assemble on sm_103) ----
__device__ __forceinline__ uint32_t smem_u32(const void* p) {
    uint32_t a;
    asm("{ .reg .u64 t; cvta.to.shared.u64 t, %1; cvt.u32.u64 %0, t; }" : "=r"(a) : "l"(p));
    return a;
}
__device__ __forceinline__ void cp16(uint32_t s, const void* g) {
    asm volatile("cp.async.cg.shared.global [%0], [%1], 16;" :: "r"(s), "l"(g));
}
#define CP_COMMIT() asm volatile("cp.async.commit_group;" ::: "memory")
#define CP_WAIT1()  asm volatile("cp.async.wait_group 1;" ::: "memory")

__device__ __forceinline__ void ldmx4(uint32_t* r, uint32_t addr) {
    asm volatile("ldmatrix.sync.aligned.m8n8.x4.shared.b16 {%0,%1,%2,%3}, [%4];"
                 : "=r"(r[0]), "=r"(r[1]), "=r"(r[2]), "=r"(r[3]) : "r"(addr));
}
__device__ __forceinline__ void mma16816(float* d, const uint32_t* a, const uint32_t* b) {
    asm volatile("mma.sync.aligned.m16n8k16.row.col.f32.bf16.bf16.f32 "
                 "{%0,%1,%2,%3}, {%4,%5,%6,%7}, {%8,%9}, {%0,%1,%2,%3};"
                 : "+f"(d[0]), "+f"(d[1]), "+f"(d[2]), "+f"(d[3])
                 : "r"(a[0]), "r"(a[1]), "r"(a[2]), "r"(a[3]), "r"(b[0]), "r"(b[1]));
}

// ---------------- converts ----------------
__global__ void cvt_hilo(const float2* __restrict__ in, __nv_bfloat162* __restrict__ hi,
                         __nv_bfloat162* __restrict__ lo, size_t n2) {
    size_t i = (size_t)blockIdx.x * blockDim.x + threadIdx.x;
    if (i >= n2) return;
    float2 v = in[i];
    __nv_bfloat16 hx = __float2bfloat16(v.x), hy = __float2bfloat16(v.y);
    __nv_bfloat162 h; h.x = hx; h.y = hy;
    __nv_bfloat162 l;
    l.x = __float2bfloat16(v.x - __bfloat162float(hx));
    l.y = __float2bfloat16(v.y - __bfloat162float(hy));
    hi[i] = h; lo[i] = l;
}

// transpose + split: in [K][N] fp32 -> out hi/lo [N][K] bf16
__global__ __launch_bounds__(256) void transpose_cvt(
    const float* __restrict__ in, __nv_bfloat16* __restrict__ hi,
    __nv_bfloat16* __restrict__ lo, int K, int N) {
    __shared__ float t[32][33];
    int n0 = blockIdx.x * 32, k0 = blockIdx.y * 32;
    int tx = threadIdx.x & 31, ty = threadIdx.x >> 5;
    #pragma unroll
    for (int i = 0; i < 4; i++)
        t[ty + 8*i][tx] = in[(size_t)(k0 + ty + 8*i) * N + n0 + tx];
    __syncthreads();
    #pragma unroll
    for (int i = 0; i < 4; i++) {
        float v = t[tx][ty + 8*i];
        size_t o = (size_t)(n0 + ty + 8*i) * K + k0 + tx;
        __nv_bfloat16 h = __float2bfloat16(v);
        hi[o] = h;
        lo[o] = __float2bfloat16(v - __bfloat162float(h));
    }
}

// ---------------- HMMA split-bf16 GEMM: C[M,N] = A[M,K] @ B[N,K]^T ----------------
// BM=128, BN=128, BK=32, 8 warps (4 in M x 2 in N -> warp tile 32x64), 3-stage cp.async.
#define KITERS (KDIM / 32)
#define TILEB  8192u               // 128 rows x 32 bf16 (64B/row)
#define STAGEB (4u * TILEB)        // Ah, Al, Bh, Bl
#define GEMM_SMEM (3 * 32768)      // 96 KB

template<bool ELU, bool BIAS>
__global__ __launch_bounds__(256, 1) void gemm_mma(
    const __nv_bfloat16* __restrict__ Ahi, const __nv_bfloat16* __restrict__ Alo,
    const __nv_bfloat16* __restrict__ Bhi, const __nv_bfloat16* __restrict__ Blo,
    const float* __restrict__ bias, float* __restrict__ C, int N)
{
    extern __shared__ char sm[];
    const uint32_t sb = smem_u32(sm);
    const int tid = threadIdx.x;
    const int lane = tid & 31, wid = tid >> 5;
    const int wm = (wid >> 1) * 32;      // warp M offset in block tile
    const int wn = (wid & 1) * 64;       // warp N offset
    const int m0 = blockIdx.y * 128, n0 = blockIdx.x * 128;

    // ---- load geometry: 2 x 16B chunk per thread per tile ----
    const int lr = tid >> 2;             // 0..63
    const int lc = tid & 3;              // chunk within row (8 bf16 each)
    uint32_t so[2]; size_t gA[2], gB[2];
    #pragma unroll
    for (int i = 0; i < 2; i++) {
        int r = lr + 64 * i;
        so[i] = (uint32_t)(r * 64 + ((lc ^ (r & 3)) << 4));
        gA[i] = (size_t)(m0 + r) * KDIM + lc * 8;
        gB[i] = (size_t)(n0 + r) * KDIM + lc * 8;
    }

    // ---- ldmatrix row geometry ----
    int ra[2], rb[4];
    #pragma unroll
    for (int mt = 0; mt < 2; mt++) ra[mt] = wm + mt * 16 + (lane & 15);
    #pragma unroll
    for (int np = 0; np < 4; np++)
        rb[np] = wn + np * 16 + (lane & 7) + ((lane & 16) ? 8 : 0);
    const int caH = lane >> 4;           // 0/1 k-half for A
    const int cbH = (lane >> 3) & 1;     // 0/1 k-half for B

    float acc[2][8][4];
    #pragma unroll
    for (int mt = 0; mt < 2; mt++)
        #pragma unroll
        for (int nt = 0; nt < 8; nt++)
            #pragma unroll
            for (int j = 0; j < 4; j++) acc[mt][nt][j] = 0.f;

    auto issue = [&](int s) {
        if (s < KITERS) {
            uint32_t st = sb + (uint32_t)(s % 3) * STAGEB;
            size_t ko = (size_t)s * 32;
            #pragma unroll
            for (int i = 0; i < 2; i++) {
                cp16(st + 0u*TILEB + so[i], Ahi + gA[i] + ko);
                cp16(st + 1u*TILEB + so[i], Alo + gA[i] + ko);
                cp16(st + 2u*TILEB + so[i], Bhi + gB[i] + ko);
                cp16(st + 3u*TILEB + so[i], Blo + gB[i] + ko);
            }
        }
        CP_COMMIT();
    };

    issue(0);
    issue(1);

    for (int s = 0; s < KITERS; s++) {
        CP_WAIT1();
        __syncthreads();
        issue(s + 2);

        const uint32_t st = sb + (uint32_t)(s % 3) * STAGEB;
        #pragma unroll
        for (int ks = 0; ks < 2; ks++) {
            uint32_t ah[2][4], al[2][4];
            #pragma unroll
            for (int mt = 0; mt < 2; mt++) {
                uint32_t c = (uint32_t)(ks * 2 + caH);
                uint32_t off = (uint32_t)(ra[mt] * 64) + ((c ^ (ra[mt] & 3)) << 4);
                ldmx4(ah[mt], st + 0u*TILEB + off);
                ldmx4(al[mt], st + 1u*TILEB + off);
            }
            #pragma unroll
            for (int np = 0; np < 4; np++) {
                uint32_t c = (uint32_t)(ks * 2 + cbH);
                uint32_t off = (uint32_t)(rb[np] * 64) + ((c ^ (rb[np] & 3)) << 4);
                uint32_t bh[4], bl[4];
                ldmx4(bh, st + 2u*TILEB + off);
                ldmx4(bl, st + 3u*TILEB + off);
                #pragma unroll
                for (int mt = 0; mt < 2; mt++) {
                    mma16816(acc[mt][2*np  ], ah[mt], bh + 0);
                    mma16816(acc[mt][2*np  ], ah[mt], bl + 0);
                    mma16816(acc[mt][2*np  ], al[mt], bh + 0);
                    mma16816(acc[mt][2*np+1], ah[mt], bh + 2);
                    mma16816(acc[mt][2*np+1], ah[mt], bl + 2);
                    mma16816(acc[mt][2*np+1], al[mt], bh + 2);
                }
            }
        }
    }

    // ---- epilogue: regs -> global with fused elu+1 / bias ----
    #pragma unroll
    for (int mt = 0; mt < 2; mt++) {
        #pragma unroll
        for (int nt = 0; nt < 8; nt++) {
            int row = m0 + wm + mt * 16 + (lane >> 2);
            int col = n0 + wn + nt * 8 + (lane & 3) * 2;
            #pragma unroll
            for (int half = 0; half < 2; half++) {
                int r = row + half * 8;
                float v0 = acc[mt][nt][half * 2 + 0];
                float v1 = acc[mt][nt][half * 2 + 1];
                if (ELU) {
                    if (col < 2048)     v0 = (v0 > 0.f) ? (v0 + 1.f) : expf(v0);
                    if (col + 1 < 2048) v1 = (v1 > 0.f) ? (v1 + 1.f) : expf(v1);
                }
                if (BIAS) { v0 += bias[col]; v1 += bias[col + 1]; }
                float2 o; o.x = v0; o.y = v1;
                *(float2*)(C + (size_t)r * N + col) = o;
            }
        }
    }
}

// ---------------- attention kernels ----------------
__global__ __launch_bounds__(256) void kv_kernel(
    const float* __restrict__ qkv, float* __restrict__ kvout, float* __restrict__ ksum)
{
    const int bh = blockIdx.x;
    const int b = bh >> 4, h = bh & 15;
    const float* kbase = qkv + (size_t)b * NN * QKVC + CC + h * DD;
    const float* vbase = qkv + (size_t)b * NN * QKVC + 2 * CC + h * DD;

    __shared__ float ks[32][64];
    __shared__ float vs[32][64];

    const int tid = threadIdx.x;
    const int e0 = (tid & 15) * 4;
    const int d0 = (tid >> 4) * 4;

    float acc[4][4];
    #pragma unroll
    for (int i = 0; i < 4; i++)
        #pragma unroll
        for (int j = 0; j < 4; j++) acc[i][j] = 0.f;
    float ksacc = 0.f;

    for (int n0 = 0; n0 < NN; n0 += 32) {
        #pragma unroll
        for (int it = 0; it < 2; it++) {
            int idx = tid + it * 256;
            int r = idx >> 4, cc2 = (idx & 15) * 4;
            *(float4*)&ks[r][cc2] = *(const float4*)(kbase + (size_t)(n0 + r) * QKVC + cc2);
            *(float4*)&vs[r][cc2] = *(const float4*)(vbase + (size_t)(n0 + r) * QKVC + cc2);
        }
        __syncthreads();
        #pragma unroll 8
        for (int nn = 0; nn < 32; nn++) {
            float kd[4], ve[4];
            *(float4*)kd = *(const float4*)&ks[nn][d0];
            *(float4*)ve = *(const float4*)&vs[nn][e0];
            #pragma unroll
            for (int i = 0; i < 4; i++)
                #pragma unroll
                for (int j = 0; j < 4; j++)
                    acc[i][j] += kd[i] * ve[j];
            if (tid < 64) ksacc += ks[nn][tid];
        }
        __syncthreads();
    }
    float* kvo = kvout + (size_t)bh * DD * DD;
    #pragma unroll
    for (int i = 0; i < 4; i++)
        #pragma unroll
        for (int j = 0; j < 4; j++)
            kvo[(d0 + i) * DD + e0 + j] = acc[i][j];
    if (tid < 64) ksum[bh * DD + tid] = ksacc;
}

// out -> bf16 hi/lo in [B,N,C] layout (feeds GEMM2 directly)
__global__ __launch_bounds__(256) void qout_kernel(
    const float* __restrict__ qkv, const float* __restrict__ kvmat,
    const float* __restrict__ ksum, __nv_bfloat16* __restrict__ ahi,
    __nv_bfloat16* __restrict__ alo)
{
    const int bh = blockIdx.y;
    const int b = bh >> 4, h = bh & 15;
    const int n0 = blockIdx.x * 64;

    __shared__ float kvs[64][64];
    __shared__ float qs[64][64];
    __shared__ float kss[64];

    const int tid = threadIdx.x;
    const float* qbase = qkv + (size_t)b * NN * QKVC + h * DD;
    const float* kvb = kvmat + (size_t)bh * DD * DD;

    #pragma unroll
    for (int it = 0; it < 4; it++) {
        int idx = tid + it * 256;
        int r = idx >> 4, c = (idx & 15) * 4;
        *(float4*)&kvs[r][c] = *(const float4*)(kvb + r * DD + c);
        *(float4*)&qs[r][c]  = *(const float4*)(qbase + (size_t)(n0 + r) * QKVC + c);
    }
    if (tid < 64) kss[tid] = ksum[bh * DD + tid];
    __syncthreads();

    const int r = tid >> 2;
    const int e0 = (tid & 3) * 16;

    float acc[16];
    #pragma unroll
    for (int j = 0; j < 16; j++) acc[j] = 0.f;
    float zden = 0.f;

    #pragma unroll
    for (int d = 0; d < 64; d++) {
        float qd = qs[r][d];
        zden += qd * kss[d];
        #pragma unroll
        for (int j = 0; j < 16; j++)
            acc[j] += qd * kvs[d][e0 + j];
    }
    float z = 1.f / (zden + 1e-6f);

    size_t obase = ((size_t)b * NN + n0 + r) * CC + h * DD + e0;
    __nv_bfloat162* oh = (__nv_bfloat162*)(ahi + obase);
    __nv_bfloat162* ol = (__nv_bfloat162*)(alo + obase);
    #pragma unroll
    for (int j = 0; j < 16; j += 2) {
        float v0 = acc[j] * z, v1 = acc[j + 1] * z;
        __nv_bfloat16 h0 = __float2bfloat16(v0), h1 = __float2bfloat16(v1);
        __nv_bfloat162 hh; hh.x = h0; hh.y = h1;
        __nv_bfloat162 ll;
        ll.x = __float2bfloat16(v0 - __bfloat162float(h0));
        ll.y = __float2bfloat16(v1 - __bfloat162float(h1));
        oh[j >> 1] = hh; ol[j >> 1] = ll;
    }
}

// ---------------------------------------------------------------------------
extern "C" void kernel_launch(void* const* d_in, const int* in_sizes, int n_in,
                              void* d_out, int out_size)
{
    const float* x     = (const float*)d_in[0];
    const float* Wqkv  = (const float*)d_in[1];
    const float* Wproj = (const float*)d_in[2];
    const float* bproj = (const float*)d_in[3];
    float* out = (float*)d_out;

    float *qkv_p, *kv_p, *ksum_p;
    __nv_bfloat16 *xhi, *xlo, *ahi, *alo, *wqh, *wql, *wph, *wpl;
    cudaGetSymbolAddress((void**)&qkv_p, g_qkv);
    cudaGetSymbolAddress((void**)&kv_p,  g_kv);
    cudaGetSymbolAddress((void**)&ksum_p, g_ksum);
    cudaGetSymbolAddress((void**)&xhi, g_xhi);
    cudaGetSymbolAddress((void**)&xlo, g_xlo);
    cudaGetSymbolAddress((void**)&ahi, g_attn_hi);
    cudaGetSymbolAddress((void**)&alo, g_attn_lo);
    cudaGetSymbolAddress((void**)&wqh, g_wqkvT_hi);
    cudaGetSymbolAddress((void**)&wql, g_wqkvT_lo);
    cudaGetSymbolAddress((void**)&wph, g_wprojT_hi);
    cudaGetSymbolAddress((void**)&wpl, g_wprojT_lo);

    cudaFuncSetAttribute(gemm_mma<true, false>,
                         cudaFuncAttributeMaxDynamicSharedMemorySize, GEMM_SMEM);
    cudaFuncSetAttribute(gemm_mma<false, true>,
                         cudaFuncAttributeMaxDynamicSharedMemorySize, GEMM_SMEM);

    // split x into bf16 hi/lo
    {
        size_t n2 = (size_t)MTOT * CC / 2;
        cvt_hilo<<<(unsigned)((n2 + 255) / 256), 256>>>(
            (const float2*)x, (__nv_bfloat162*)xhi, (__nv_bfloat162*)xlo, n2);
    }
    // transpose + split weights to [N][K] bf16 hi/lo
    transpose_cvt<<<dim3(QKVC / 32, KDIM / 32), 256>>>(Wqkv, wqh, wql, KDIM, QKVC);
    transpose_cvt<<<dim3(CC / 32, KDIM / 32), 256>>>(Wproj, wph, wpl, KDIM, CC);

    // GEMM1: qkv = x @ W_qkv  (fused elu+1 on cols < 2048)
    gemm_mma<true, false><<<dim3(QKVC / 128, MTOT / 128), 256, GEMM_SMEM>>>(
        xhi, xlo, wqh, wql, nullptr, qkv_p, QKVC);

    // attention state + output
    kv_kernel<<<BB * HH, 256>>>(qkv_p, kv_p, ksum_p);
    qout_kernel<<<dim3(NN / 64, BB * HH), 256>>>(qkv_p, kv_p, ksum_p, ahi, alo);

    // GEMM2: out = attn @ W_proj + b_proj
    gemm_mma<false, true><<<dim3(CC / 128, MTOT / 128), 256, GEMM_SMEM>>>(
        ahi, alo, wph, wpl, bproj, out, CC);
}

// round 5
// speedup vs baseline: 2.2481x; 1.1560x over previous
#include <cuda_runtime.h>
#include <cuda_bf16.h>
#include <math.h>
#include <cstdint>

#define BB 4
#define NN 4096
#define CC 1024
#define HH 16
#define DD 64
#define MTOT (BB*NN)        // 16384
#define QKVC (3*CC)         // 3072
#define KDIM 1024
#define KVCHUNK 4

// ---------------- scratch (device globals; allocation-free) ----------------
__device__ float g_qkv[(size_t)MTOT * QKVC];
__device__ __nv_bfloat16 g_xhi[(size_t)MTOT * CC];
__device__ __nv_bfloat16 g_xlo[(size_t)MTOT * CC];
__device__ __nv_bfloat16 g_attn_hi[(size_t)MTOT * CC];
__device__ __nv_bfloat16 g_attn_lo[(size_t)MTOT * CC];
__device__ __nv_bfloat16 g_wqkvT_hi[(size_t)QKVC * KDIM];
__device__ __nv_bfloat16 g_wqkvT_lo[(size_t)QKVC * KDIM];
__device__ __nv_bfloat16 g_wprojT_hi[(size_t)CC * KDIM];
__device__ __nv_bfloat16 g_wprojT_lo[(size_t)CC * KDIM];
__device__ float g_kvp[KVCHUNK * BB*HH*DD*DD];   // partial kv per chunk
__device__ float g_ksump[KVCHUNK * BB*HH*DD];
__device__ float g_kv[BB*HH*DD*DD];
__device__ float g_ksum[BB*HH*DD];

// ---------------- PTX helpers (baseline sm_80-class; assemble on sm_103) ----
__device__ __forceinline__ uint32_t smem_u32(const void* p) {
    uint32_t a;
    asm("{ .reg .u64 t; cvta.to.shared.u64 t, %1; cvt.u32.u64 %0, t; }" : "=r"(a) : "l"(p));
    return a;
}
__device__ __forceinline__ void cp16(uint32_t s, const void* g) {
    asm volatile("cp.async.cg.shared.global [%0], [%1], 16;" :: "r"(s), "l"(g));
}
#define CP_COMMIT() asm volatile("cp.async.commit_group;" ::: "memory")
#define CP_WAIT1()  asm volatile("cp.async.wait_group 1;" ::: "memory")

__device__ __forceinline__ void ldmx4(uint32_t* r, uint32_t addr) {
    asm volatile("ldmatrix.sync.aligned.m8n8.x4.shared.b16 {%0,%1,%2,%3}, [%4];"
                 : "=r"(r[0]), "=r"(r[1]), "=r"(r[2]), "=r"(r[3]) : "r"(addr));
}
__device__ __forceinline__ void mma16816(float* d, const uint32_t* a, const uint32_t* b) {
    asm volatile("mma.sync.aligned.m16n8k16.row.col.f32.bf16.bf16.f32 "
                 "{%0,%1,%2,%3}, {%4,%5,%6,%7}, {%8,%9}, {%0,%1,%2,%3};"
                 : "+f"(d[0]), "+f"(d[1]), "+f"(d[2]), "+f"(d[3])
                 : "r"(a[0]), "r"(a[1]), "r"(a[2]), "r"(a[3]), "r"(b[0]), "r"(b[1]));
}

// ---------------- converts ----------------
__global__ void cvt_hilo(const float2* __restrict__ in, __nv_bfloat162* __restrict__ hi,
                         __nv_bfloat162* __restrict__ lo, size_t n2) {
    size_t i = (size_t)blockIdx.x * blockDim.x + threadIdx.x;
    if (i >= n2) return;
    float2 v = in[i];
    __nv_bfloat16 hx = __float2bfloat16(v.x), hy = __float2bfloat16(v.y);
    __nv_bfloat162 h; h.x = hx; h.y = hy;
    __nv_bfloat162 l;
    l.x = __float2bfloat16(v.x - __bfloat162float(hx));
    l.y = __float2bfloat16(v.y - __bfloat162float(hy));
    hi[i] = h; lo[i] = l;
}

__global__ __launch_bounds__(256) void transpose_cvt(
    const float* __restrict__ in, __nv_bfloat16* __restrict__ hi,
    __nv_bfloat16* __restrict__ lo, int K, int N) {
    __shared__ float t[32][33];
    int n0 = blockIdx.x * 32, k0 = blockIdx.y * 32;
    int tx = threadIdx.x & 31, ty = threadIdx.x >> 5;
    #pragma unroll
    for (int i = 0; i < 4; i++)
        t[ty + 8*i][tx] = in[(size_t)(k0 + ty + 8*i) * N + n0 + tx];
    __syncthreads();
    #pragma unroll
    for (int i = 0; i < 4; i++) {
        float v = t[tx][ty + 8*i];
        size_t o = (size_t)(n0 + ty + 8*i) * K + k0 + tx;
        __nv_bfloat16 h = __float2bfloat16(v);
        hi[o] = h;
        lo[o] = __float2bfloat16(v - __bfloat162float(h));
    }
}

// ---------------- HMMA split-bf16 GEMM: C[M,N] = A[M,K] @ B[N,K]^T ----------------
// Block tile 256x128, BK=32, 8 warps (4M x 2N), warp tile 64x64, 3-stage cp.async.
#define KITERS (KDIM / 32)
#define AHB 16384u               // Ah: 256 rows x 64B
#define BHB 8192u                // Bh: 128 rows x 64B
#define STAGEB (2u*AHB + 2u*BHB) // 49152
#define GEMM_SMEM (3 * 49152)    // 147456

template<bool ELU, bool BIAS>
__global__ __launch_bounds__(256, 1) void gemm_mma(
    const __nv_bfloat16* __restrict__ Ahi, const __nv_bfloat16* __restrict__ Alo,
    const __nv_bfloat16* __restrict__ Bhi, const __nv_bfloat16* __restrict__ Blo,
    const float* __restrict__ bias, float* __restrict__ C, int N)
{
    extern __shared__ char sm[];
    const uint32_t sb = smem_u32(sm);
    const int tid = threadIdx.x;
    const int lane = tid & 31, wid = tid >> 5;
    const int wm = (wid >> 1) * 64;      // warp M offset (0,64,128,192)
    const int wn = (wid & 1) * 64;       // warp N offset (0,64)
    const int m0 = blockIdx.y * 256, n0 = blockIdx.x * 128;

    // ---- cp.async geometry ----
    const int lr = tid >> 2;             // 0..63
    const int lc = tid & 3;              // 16B chunk in 64B row
    const uint32_t cx = (uint32_t)((lc ^ (lr & 3)) << 4);
    uint32_t soA[4], soB[2]; size_t gA[4], gB[2];
    #pragma unroll
    for (int i = 0; i < 4; i++) {
        int r = lr + 64 * i;
        soA[i] = (uint32_t)(r * 64) + cx;
        gA[i] = (size_t)(m0 + r) * KDIM + lc * 8;
    }
    #pragma unroll
    for (int i = 0; i < 2; i++) {
        int r = lr + 64 * i;
        soB[i] = (uint32_t)(r * 64) + cx;
        gB[i] = (size_t)(n0 + r) * KDIM + lc * 8;
    }

    // ---- ldmatrix geometry ----
    int ra[4], rb[4];
    #pragma unroll
    for (int mt = 0; mt < 4; mt++) ra[mt] = wm + mt * 16 + (lane & 15);
    #pragma unroll
    for (int np = 0; np < 4; np++)
        rb[np] = wn + np * 16 + (lane & 7) + ((lane & 16) ? 8 : 0);
    const int caH = lane >> 4;
    const int cbH = (lane >> 3) & 1;

    float acc[4][8][4];
    #pragma unroll
    for (int mt = 0; mt < 4; mt++)
        #pragma unroll
        for (int nt = 0; nt < 8; nt++)
            #pragma unroll
            for (int j = 0; j < 4; j++) acc[mt][nt][j] = 0.f;

    auto issue = [&](int s) {
        if (s < KITERS) {
            uint32_t st = sb + (uint32_t)(s % 3) * STAGEB;
            size_t ko = (size_t)s * 32;
            #pragma unroll
            for (int i = 0; i < 4; i++) {
                cp16(st + soA[i],       Ahi + gA[i] + ko);
                cp16(st + AHB + soA[i], Alo + gA[i] + ko);
            }
            #pragma unroll
            for (int i = 0; i < 2; i++) {
                cp16(st + 2u*AHB + soB[i],       Bhi + gB[i] + ko);
                cp16(st + 2u*AHB + BHB + soB[i], Blo + gB[i] + ko);
            }
        }
        CP_COMMIT();
    };

    issue(0);
    issue(1);

    for (int s = 0; s < KITERS; s++) {
        CP_WAIT1();
        __syncthreads();
        issue(s + 2);

        const uint32_t st = sb + (uint32_t)(s % 3) * STAGEB;
        #pragma unroll
        for (int ks = 0; ks < 2; ks++) {
            uint32_t ah[4][4], al[4][4];
            #pragma unroll
            for (int mt = 0; mt < 4; mt++) {
                uint32_t c = (uint32_t)(ks * 2 + caH);
                uint32_t off = (uint32_t)(ra[mt] * 64) + ((c ^ (ra[mt] & 3)) << 4);
                ldmx4(ah[mt], st + off);
                ldmx4(al[mt], st + AHB + off);
            }
            #pragma unroll
            for (int np = 0; np < 4; np++) {
                uint32_t c = (uint32_t)(ks * 2 + cbH);
                uint32_t off = (uint32_t)(rb[np] * 64) + ((c ^ (rb[np] & 3)) << 4);
                uint32_t bh[4], bl[4];
                ldmx4(bh, st + 2u*AHB + off);
                ldmx4(bl, st + 2u*AHB + BHB + off);
                #pragma unroll
                for (int mt = 0; mt < 4; mt++) {
                    mma16816(acc[mt][2*np  ], ah[mt], bh + 0);
                    mma16816(acc[mt][2*np  ], ah[mt], bl + 0);
                    mma16816(acc[mt][2*np  ], al[mt], bh + 0);
                    mma16816(acc[mt][2*np+1], ah[mt], bh + 2);
                    mma16816(acc[mt][2*np+1], ah[mt], bl + 2);
                    mma16816(acc[mt][2*np+1], al[mt], bh + 2);
                }
            }
        }
    }

    // ---- epilogue ----
    #pragma unroll
    for (int mt = 0; mt < 4; mt++) {
        #pragma unroll
        for (int nt = 0; nt < 8; nt++) {
            int row = m0 + wm + mt * 16 + (lane >> 2);
            int col = n0 + wn + nt * 8 + (lane & 3) * 2;
            #pragma unroll
            for (int half = 0; half < 2; half++) {
                int r = row + half * 8;
                float v0 = acc[mt][nt][half * 2 + 0];
                float v1 = acc[mt][nt][half * 2 + 1];
                if (ELU) {
                    if (col < 2048)     v0 = (v0 > 0.f) ? (v0 + 1.f) : expf(v0);
                    if (col + 1 < 2048) v1 = (v1 > 0.f) ? (v1 + 1.f) : expf(v1);
                }
                if (BIAS) { v0 += bias[col]; v1 += bias[col + 1]; }
                float2 o; o.x = v0; o.y = v1;
                *(float2*)(C + (size_t)r * N + col) = o;
            }
        }
    }
}

// ---------------- attention: kv partial over N-chunk ----------------
__global__ __launch_bounds__(256) void kv_part_kernel(
    const float* __restrict__ qkv, float* __restrict__ kvp, float* __restrict__ ksump)
{
    const int bx = blockIdx.x;          // 0..255
    const int bh = bx >> 2, chunk = bx & 3;
    const int b = bh >> 4, h = bh & 15;
    const int nbeg = chunk * (NN / KVCHUNK), nend = nbeg + NN / KVCHUNK;
    const float* kbase = qkv + (size_t)b * NN * QKVC + CC + h * DD;
    const float* vbase = qkv + (size_t)b * NN * QKVC + 2 * CC + h * DD;

    __shared__ float ks[32][64];
    __shared__ float vs[32][64];

    const int tid = threadIdx.x;
    const int e0 = (tid & 15) * 4;
    const int d0 = (tid >> 4) * 4;

    float acc[4][4];
    #pragma unroll
    for (int i = 0; i < 4; i++)
        #pragma unroll
        for (int j = 0; j < 4; j++) acc[i][j] = 0.f;
    float ksacc = 0.f;

    for (int n0 = nbeg; n0 < nend; n0 += 32) {
        #pragma unroll
        for (int it = 0; it < 2; it++) {
            int idx = tid + it * 256;
            int r = idx >> 4, cc2 = (idx & 15) * 4;
            *(float4*)&ks[r][cc2] = *(const float4*)(kbase + (size_t)(n0 + r) * QKVC + cc2);
            *(float4*)&vs[r][cc2] = *(const float4*)(vbase + (size_t)(n0 + r) * QKVC + cc2);
        }
        __syncthreads();
        #pragma unroll 8
        for (int nn = 0; nn < 32; nn++) {
            float kd[4], ve[4];
            *(float4*)kd = *(const float4*)&ks[nn][d0];
            *(float4*)ve = *(const float4*)&vs[nn][e0];
            #pragma unroll
            for (int i = 0; i < 4; i++)
                #pragma unroll
                for (int j = 0; j < 4; j++)
                    acc[i][j] += kd[i] * ve[j];
            if (tid < 64) ksacc += ks[nn][tid];
        }
        __syncthreads();
    }
    float* kvo = kvp + (size_t)bx * DD * DD;
    #pragma unroll
    for (int i = 0; i < 4; i++)
        #pragma unroll
        for (int j = 0; j < 4; j++)
            kvo[(d0 + i) * DD + e0 + j] = acc[i][j];
    if (tid < 64) ksump[bx * DD + tid] = ksacc;
}

__global__ __launch_bounds__(256) void kv_reduce_kernel(
    const float* __restrict__ kvp, const float* __restrict__ ksump,
    float* __restrict__ kv, float* __restrict__ ksum)
{
    const int bh = blockIdx.x;
    const int tid = threadIdx.x;
    #pragma unroll
    for (int e = 0; e < 16; e++) {
        int idx = tid + e * 256;
        float s = 0.f;
        #pragma unroll
        for (int c = 0; c < KVCHUNK; c++)
            s += kvp[(size_t)(bh * KVCHUNK + c) * DD * DD + idx];
        kv[(size_t)bh * DD * DD + idx] = s;
    }
    if (tid < DD) {
        float s = 0.f;
        #pragma unroll
        for (int c = 0; c < KVCHUNK; c++)
            s += ksump[(bh * KVCHUNK + c) * DD + tid];
        ksum[bh * DD + tid] = s;
    }
}

// out -> bf16 hi/lo in [B,N,C] layout (feeds GEMM2 directly)
__global__ __launch_bounds__(256) void qout_kernel(
    const float* __restrict__ qkv, const float* __restrict__ kvmat,
    const float* __restrict__ ksum, __nv_bfloat16* __restrict__ ahi,
    __nv_bfloat16* __restrict__ alo)
{
    const int bh = blockIdx.y;
    const int b = bh >> 4, h = bh & 15;
    const int n0 = blockIdx.x * 64;

    __shared__ float kvs[64][64];
    __shared__ float qs[64][64];
    __shared__ float kss[64];

    const int tid = threadIdx.x;
    const float* qbase = qkv + (size_t)b * NN * QKVC + h * DD;
    const float* kvb = kvmat + (size_t)bh * DD * DD;

    #pragma unroll
    for (int it = 0; it < 4; it++) {
        int idx = tid + it * 256;
        int r = idx >> 4, c = (idx & 15) * 4;
        *(float4*)&kvs[r][c] = *(const float4*)(kvb + r * DD + c);
        *(float4*)&qs[r][c]  = *(const float4*)(qbase + (size_t)(n0 + r) * QKVC + c);
    }
    if (tid < 64) kss[tid] = ksum[bh * DD + tid];
    __syncthreads();

    const int r = tid >> 2;
    const int e0 = (tid & 3) * 16;

    float acc[16];
    #pragma unroll
    for (int j = 0; j < 16; j++) acc[j] = 0.f;
    float zden = 0.f;

    #pragma unroll
    for (int d = 0; d < 64; d++) {
        float qd = qs[r][d];
        zden += qd * kss[d];
        #pragma unroll
        for (int j = 0; j < 16; j++)
            acc[j] += qd * kvs[d][e0 + j];
    }
    float z = 1.f / (zden + 1e-6f);

    size_t obase = ((size_t)b * NN + n0 + r) * CC + h * DD + e0;
    __nv_bfloat162* oh = (__nv_bfloat162*)(ahi + obase);
    __nv_bfloat162* ol = (__nv_bfloat162*)(alo + obase);
    #pragma unroll
    for (int j = 0; j < 16; j += 2) {
        float v0 = acc[j] * z, v1 = acc[j + 1] * z;
        __nv_bfloat16 h0 = __float2bfloat16(v0), h1 = __float2bfloat16(v1);
        __nv_bfloat162 hh; hh.x = h0; hh.y = h1;
        __nv_bfloat162 ll;
        ll.x = __float2bfloat16(v0 - __bfloat162float(h0));
        ll.y = __float2bfloat16(v1 - __bfloat162float(h1));
        oh[j >> 1] = hh; ol[j >> 1] = ll;
    }
}

// ---------------------------------------------------------------------------
extern "C" void kernel_launch(void* const* d_in, const int* in_sizes, int n_in,
                              void* d_out, int out_size)
{
    const float* x     = (const float*)d_in[0];
    const float* Wqkv  = (const float*)d_in[1];
    const float* Wproj = (const float*)d_in[2];
    const float* bproj = (const float*)d_in[3];
    float* out = (float*)d_out;

    float *qkv_p, *kv_p, *ksum_p, *kvp_p, *ksump_p;
    __nv_bfloat16 *xhi, *xlo, *ahi, *alo, *wqh, *wql, *wph, *wpl;
    cudaGetSymbolAddress((void**)&qkv_p, g_qkv);
    cudaGetSymbolAddress((void**)&kv_p,  g_kv);
    cudaGetSymbolAddress((void**)&ksum_p, g_ksum);
    cudaGetSymbolAddress((void**)&kvp_p,  g_kvp);
    cudaGetSymbolAddress((void**)&ksump_p, g_ksump);
    cudaGetSymbolAddress((void**)&xhi, g_xhi);
    cudaGetSymbolAddress((void**)&xlo, g_xlo);
    cudaGetSymbolAddress((void**)&ahi, g_attn_hi);
    cudaGetSymbolAddress((void**)&alo, g_attn_lo);
    cudaGetSymbolAddress((void**)&wqh, g_wqkvT_hi);
    cudaGetSymbolAddress((void**)&wql, g_wqkvT_lo);
    cudaGetSymbolAddress((void**)&wph, g_wprojT_hi);
    cudaGetSymbolAddress((void**)&wpl, g_wprojT_lo);

    cudaFuncSetAttribute(gemm_mma<true, false>,
                         cudaFuncAttributeMaxDynamicSharedMemorySize, GEMM_SMEM);
    cudaFuncSetAttribute(gemm_mma<false, true>,
                         cudaFuncAttributeMaxDynamicSharedMemorySize, GEMM_SMEM);

    // split x into bf16 hi/lo
    {
        size_t n2 = (size_t)MTOT * CC / 2;
        cvt_hilo<<<(unsigned)((n2 + 255) / 256), 256>>>(
            (const float2*)x, (__nv_bfloat162*)xhi, (__nv_bfloat162*)xlo, n2);
    }
    // transpose + split weights to [N][K] bf16 hi/lo
    transpose_cvt<<<dim3(QKVC / 32, KDIM / 32), 256>>>(Wqkv, wqh, wql, KDIM, QKVC);
    transpose_cvt<<<dim3(CC / 32, KDIM / 32), 256>>>(Wproj, wph, wpl, KDIM, CC);

    // GEMM1: qkv = x @ W_qkv  (fused elu+1 on cols < 2048)
    gemm_mma<true, false><<<dim3(QKVC / 128, MTOT / 256), 256, GEMM_SMEM>>>(
        xhi, xlo, wqh, wql, nullptr, qkv_p, QKVC);

    // attention state (4-way N-split, deterministic reduce) + output
    kv_part_kernel<<<BB * HH * KVCHUNK, 256>>>(qkv_p, kvp_p, ksump_p);
    kv_reduce_kernel<<<BB * HH, 256>>>(kvp_p, ksump_p, kv_p, ksum_p);
    qout_kernel<<<dim3(NN / 64, BB * HH), 256>>>(qkv_p, kv_p, ksum_p, ahi, alo);

    // GEMM2: out = attn @ W_proj + b_proj
    gemm_mma<false, true><<<dim3(CC / 128, MTOT / 256), 256, GEMM_SMEM>>>(
        ahi, alo, wph, wpl, bproj, out, CC);
}

// round 6
// speedup vs baseline: 2.5304x; 1.1256x over previous
#include <cuda_runtime.h>
#include <cuda_bf16.h>
#include <math.h>
#include <cstdint>

#define BB 4
#define NN 4096
#define CC 1024
#define HH 16
#define DD 64
#define MTOT (BB*NN)        // 16384
#define QKVC (3*CC)         // 3072
#define KDIM 1024
#define KVCHUNK 8

// ---------------- scratch (device globals; allocation-free) ----------------
__device__ float g_qkv[(size_t)MTOT * QKVC];
__device__ __nv_bfloat16 g_xhi[(size_t)MTOT * CC];
__device__ __nv_bfloat16 g_xlo[(size_t)MTOT * CC];
__device__ __nv_bfloat16 g_attn_hi[(size_t)MTOT * CC];
__device__ __nv_bfloat16 g_attn_lo[(size_t)MTOT * CC];
__device__ __nv_bfloat16 g_wqkvT_hi[(size_t)QKVC * KDIM];
__device__ __nv_bfloat16 g_wqkvT_lo[(size_t)QKVC * KDIM];
__device__ __nv_bfloat16 g_wprojT_hi[(size_t)CC * KDIM];
__device__ __nv_bfloat16 g_wprojT_lo[(size_t)CC * KDIM];
__device__ float g_kvp[KVCHUNK * BB*HH*DD*DD];
__device__ float g_ksump[KVCHUNK * BB*HH*DD];
__device__ float g_kv[BB*HH*DD*DD];
__device__ float g_ksum[BB*HH*DD];

// ---------------- PTX helpers (baseline sm_80-class; assemble on sm_103) ----
__device__ __forceinline__ uint32_t smem_u32(const void* p) {
    uint32_t a;
    asm("{ .reg .u64 t; cvta.to.shared.u64 t, %1; cvt.u32.u64 %0, t; }" : "=r"(a) : "l"(p));
    return a;
}
__device__ __forceinline__ void cp16(uint32_t s, const void* g) {
    asm volatile("cp.async.cg.shared.global [%0], [%1], 16;" :: "r"(s), "l"(g));
}
#define CP_COMMIT() asm volatile("cp.async.commit_group;" ::: "memory")
#define CP_WAIT0()  asm volatile("cp.async.wait_group 0;" ::: "memory")

__device__ __forceinline__ void ldmx4(uint32_t* r, uint32_t addr) {
    asm volatile("ldmatrix.sync.aligned.m8n8.x4.shared.b16 {%0,%1,%2,%3}, [%4];"
                 : "=r"(r[0]), "=r"(r[1]), "=r"(r[2]), "=r"(r[3]) : "r"(addr));
}
__device__ __forceinline__ void mma16816(float* d, const uint32_t* a, const uint32_t* b) {
    asm volatile("mma.sync.aligned.m16n8k16.row.col.f32.bf16.bf16.f32 "
                 "{%0,%1,%2,%3}, {%4,%5,%6,%7}, {%8,%9}, {%0,%1,%2,%3};"
                 : "+f"(d[0]), "+f"(d[1]), "+f"(d[2]), "+f"(d[3])
                 : "r"(a[0]), "r"(a[1]), "r"(a[2]), "r"(a[3]), "r"(b[0]), "r"(b[1]));
}

// ---------------- converts ----------------
__global__ void cvt_hilo(const float2* __restrict__ in, __nv_bfloat162* __restrict__ hi,
                         __nv_bfloat162* __restrict__ lo, size_t n2) {
    size_t i = (size_t)blockIdx.x * blockDim.x + threadIdx.x;
    if (i >= n2) return;
    float2 v = in[i];
    __nv_bfloat16 hx = __float2bfloat16(v.x), hy = __float2bfloat16(v.y);
    __nv_bfloat162 h; h.x = hx; h.y = hy;
    __nv_bfloat162 l;
    l.x = __float2bfloat16(v.x - __bfloat162float(hx));
    l.y = __float2bfloat16(v.y - __bfloat162float(hy));
    hi[i] = h; lo[i] = l;
}

__global__ __launch_bounds__(256) void transpose_cvt(
    const float* __restrict__ in, __nv_bfloat16* __restrict__ hi,
    __nv_bfloat16* __restrict__ lo, int K, int N) {
    __shared__ float t[32][33];
    int n0 = blockIdx.x * 32, k0 = blockIdx.y * 32;
    int tx = threadIdx.x & 31, ty = threadIdx.x >> 5;
    #pragma unroll
    for (int i = 0; i < 4; i++)
        t[ty + 8*i][tx] = in[(size_t)(k0 + ty + 8*i) * N + n0 + tx];
    __syncthreads();
    #pragma unroll
    for (int i = 0; i < 4; i++) {
        float v = t[tx][ty + 8*i];
        size_t o = (size_t)(n0 + ty + 8*i) * K + k0 + tx;
        __nv_bfloat16 h = __float2bfloat16(v);
        hi[o] = h;
        lo[o] = __float2bfloat16(v - __bfloat162float(h));
    }
}

// ---------------- HMMA split-bf16 GEMM: C[M,N] = A[M,K] @ B[N,K]^T ----------------
// Block tile 256x128, BK=64, 8 warps (4M x 2N), warp tile 64x64, 2-stage cp.async.
#define KITERS (KDIM / 64)       // 16
#define AHB 32768u               // Ah: 256 rows x 128B
#define BHB 16384u               // Bh: 128 rows x 128B
#define STAGEB (2u*AHB + 2u*BHB) // 98304
#define GEMM_SMEM (2 * 98304)    // 196608

template<bool ELU, bool BIAS>
__global__ __launch_bounds__(256, 1) void gemm_mma(
    const __nv_bfloat16* __restrict__ Ahi, const __nv_bfloat16* __restrict__ Alo,
    const __nv_bfloat16* __restrict__ Bhi, const __nv_bfloat16* __restrict__ Blo,
    const float* __restrict__ bias, float* __restrict__ C, int N)
{
    extern __shared__ char sm[];
    const uint32_t sb = smem_u32(sm);
    const int tid = threadIdx.x;
    const int lane = tid & 31, wid = tid >> 5;
    const int wm = (wid >> 1) * 64;      // warp M offset (0,64,128,192)
    const int wn = (wid & 1) * 64;       // warp N offset (0,64)
    const int m0 = blockIdx.y * 256, n0 = blockIdx.x * 128;

    // ---- cp.async geometry: 128B rows, 8 chunks of 16B, 8-way XOR swizzle ----
    const int ch = tid & 7;              // chunk in row
    const int rbase = tid >> 3;          // 0..31
    uint32_t soA[8], soB[4]; size_t gA[8], gB[4];
    #pragma unroll
    for (int i = 0; i < 8; i++) {
        int r = rbase + 32 * i;
        soA[i] = (uint32_t)(r * 128) + (uint32_t)((ch ^ (r & 7)) << 4);
        gA[i] = (size_t)(m0 + r) * KDIM + ch * 8;
    }
    #pragma unroll
    for (int i = 0; i < 4; i++) {
        int r = rbase + 32 * i;
        soB[i] = (uint32_t)(r * 128) + (uint32_t)((ch ^ (r & 7)) << 4);
        gB[i] = (size_t)(n0 + r) * KDIM + ch * 8;
    }

    // ---- ldmatrix geometry ----
    int ra[4], rb[4];
    #pragma unroll
    for (int mt = 0; mt < 4; mt++) ra[mt] = wm + mt * 16 + (lane & 15);
    #pragma unroll
    for (int np = 0; np < 4; np++)
        rb[np] = wn + np * 16 + (lane & 7) + ((lane & 16) ? 8 : 0);
    const int caH = lane >> 4;
    const int cbH = (lane >> 3) & 1;

    float acc[4][8][4];
    #pragma unroll
    for (int mt = 0; mt < 4; mt++)
        #pragma unroll
        for (int nt = 0; nt < 8; nt++)
            #pragma unroll
            for (int j = 0; j < 4; j++) acc[mt][nt][j] = 0.f;

    auto issue = [&](int s) {
        if (s < KITERS) {
            uint32_t st = sb + (uint32_t)(s & 1) * STAGEB;
            size_t ko = (size_t)s * 64;
            #pragma unroll
            for (int i = 0; i < 8; i++) {
                cp16(st + soA[i],       Ahi + gA[i] + ko);
                cp16(st + AHB + soA[i], Alo + gA[i] + ko);
            }
            #pragma unroll
            for (int i = 0; i < 4; i++) {
                cp16(st + 2u*AHB + soB[i],       Bhi + gB[i] + ko);
                cp16(st + 2u*AHB + BHB + soB[i], Blo + gB[i] + ko);
            }
        }
        CP_COMMIT();
    };

    issue(0);

    for (int s = 0; s < KITERS; s++) {
        CP_WAIT0();
        __syncthreads();
        issue(s + 1);     // overlaps with compute below

        const uint32_t st = sb + (uint32_t)(s & 1) * STAGEB;
        #pragma unroll
        for (int ks = 0; ks < 4; ks++) {
            uint32_t ah[4][4], al[4][4];
            #pragma unroll
            for (int mt = 0; mt < 4; mt++) {
                uint32_t c = (uint32_t)(ks * 2 + caH);
                uint32_t off = (uint32_t)(ra[mt] * 128) + ((c ^ (ra[mt] & 7)) << 4);
                ldmx4(ah[mt], st + off);
                ldmx4(al[mt], st + AHB + off);
            }
            #pragma unroll
            for (int np = 0; np < 4; np++) {
                uint32_t c = (uint32_t)(ks * 2 + cbH);
                uint32_t off = (uint32_t)(rb[np] * 128) + ((c ^ (rb[np] & 7)) << 4);
                uint32_t bh[4], bl[4];
                ldmx4(bh, st + 2u*AHB + off);
                ldmx4(bl, st + 2u*AHB + BHB + off);
                #pragma unroll
                for (int mt = 0; mt < 4; mt++) {
                    mma16816(acc[mt][2*np  ], ah[mt], bh + 0);
                    mma16816(acc[mt][2*np  ], ah[mt], bl + 0);
                    mma16816(acc[mt][2*np  ], al[mt], bh + 0);
                    mma16816(acc[mt][2*np+1], ah[mt], bh + 2);
                    mma16816(acc[mt][2*np+1], ah[mt], bl + 2);
                    mma16816(acc[mt][2*np+1], al[mt], bh + 2);
                }
            }
        }
        __syncthreads();   // all warps done reading stage s before next overwrite
    }

    // ---- epilogue ----
    #pragma unroll
    for (int mt = 0; mt < 4; mt++) {
        #pragma unroll
        for (int nt = 0; nt < 8; nt++) {
            int row = m0 + wm + mt * 16 + (lane >> 2);
            int col = n0 + wn + nt * 8 + (lane & 3) * 2;
            #pragma unroll
            for (int half = 0; half < 2; half++) {
                int r = row + half * 8;
                float v0 = acc[mt][nt][half * 2 + 0];
                float v1 = acc[mt][nt][half * 2 + 1];
                if (ELU) {
                    if (col < 2048)     v0 = (v0 > 0.f) ? (v0 + 1.f) : expf(v0);
                    if (col + 1 < 2048) v1 = (v1 > 0.f) ? (v1 + 1.f) : expf(v1);
                }
                if (BIAS) { v0 += bias[col]; v1 += bias[col + 1]; }
                float2 o; o.x = v0; o.y = v1;
                *(float2*)(C + (size_t)r * N + col) = o;
            }
        }
    }
}

// ---------------- attention: kv partial over N-chunk ----------------
__global__ __launch_bounds__(256) void kv_part_kernel(
    const float* __restrict__ qkv, float* __restrict__ kvp, float* __restrict__ ksump)
{
    const int bx = blockIdx.x;          // 0..511
    const int bh = bx >> 3, chunk = bx & 7;
    const int b = bh >> 4, h = bh & 15;
    const int nbeg = chunk * (NN / KVCHUNK), nend = nbeg + NN / KVCHUNK;
    const float* kbase = qkv + (size_t)b * NN * QKVC + CC + h * DD;
    const float* vbase = qkv + (size_t)b * NN * QKVC + 2 * CC + h * DD;

    __shared__ float ks[32][64];
    __shared__ float vs[32][64];

    const int tid = threadIdx.x;
    const int e0 = (tid & 15) * 4;
    const int d0 = (tid >> 4) * 4;

    float acc[4][4];
    #pragma unroll
    for (int i = 0; i < 4; i++)
        #pragma unroll
        for (int j = 0; j < 4; j++) acc[i][j] = 0.f;
    float ksacc = 0.f;

    for (int n0 = nbeg; n0 < nend; n0 += 32) {
        #pragma unroll
        for (int it = 0; it < 2; it++) {
            int idx = tid + it * 256;
            int r = idx >> 4, cc2 = (idx & 15) * 4;
            *(float4*)&ks[r][cc2] = *(const float4*)(kbase + (size_t)(n0 + r) * QKVC + cc2);
            *(float4*)&vs[r][cc2] = *(const float4*)(vbase + (size_t)(n0 + r) * QKVC + cc2);
        }
        __syncthreads();
        #pragma unroll 8
        for (int nn = 0; nn < 32; nn++) {
            float kd[4], ve[4];
            *(float4*)kd = *(const float4*)&ks[nn][d0];
            *(float4*)ve = *(const float4*)&vs[nn][e0];
            #pragma unroll
            for (int i = 0; i < 4; i++)
                #pragma unroll
                for (int j = 0; j < 4; j++)
                    acc[i][j] += kd[i] * ve[j];
            if (tid < 64) ksacc += ks[nn][tid];
        }
        __syncthreads();
    }
    float* kvo = kvp + (size_t)bx * DD * DD;
    #pragma unroll
    for (int i = 0; i < 4; i++)
        #pragma unroll
        for (int j = 0; j < 4; j++)
            kvo[(d0 + i) * DD + e0 + j] = acc[i][j];
    if (tid < 64) ksump[bx * DD + tid] = ksacc;
}

__global__ __launch_bounds__(256) void kv_reduce_kernel(
    const float* __restrict__ kvp, const float* __restrict__ ksump,
    float* __restrict__ kv, float* __restrict__ ksum)
{
    const int bh = blockIdx.x;
    const int tid = threadIdx.x;
    #pragma unroll
    for (int e = 0; e < 16; e++) {
        int idx = tid + e * 256;
        float s = 0.f;
        #pragma unroll
        for (int c = 0; c < KVCHUNK; c++)
            s += kvp[(size_t)(bh * KVCHUNK + c) * DD * DD + idx];
        kv[(size_t)bh * DD * DD + idx] = s;
    }
    if (tid < DD) {
        float s = 0.f;
        #pragma unroll
        for (int c = 0; c < KVCHUNK; c++)
            s += ksump[(bh * KVCHUNK + c) * DD + tid];
        ksum[bh * DD + tid] = s;
    }
}

// out -> bf16 hi/lo in [B,N,C] layout (feeds GEMM2 directly)
__global__ __launch_bounds__(256) void qout_kernel(
    const float* __restrict__ qkv, const float* __restrict__ kvmat,
    const float* __restrict__ ksum, __nv_bfloat16* __restrict__ ahi,
    __nv_bfloat16* __restrict__ alo)
{
    const int bh = blockIdx.y;
    const int b = bh >> 4, h = bh & 15;
    const int n0 = blockIdx.x * 64;

    __shared__ float kvs[64][64];
    __shared__ float qs[64][64];
    __shared__ float kss[64];

    const int tid = threadIdx.x;
    const float* qbase = qkv + (size_t)b * NN * QKVC + h * DD;
    const float* kvb = kvmat + (size_t)bh * DD * DD;

    #pragma unroll
    for (int it = 0; it < 4; it++) {
        int idx = tid + it * 256;
        int r = idx >> 4, c = (idx & 15) * 4;
        *(float4*)&kvs[r][c] = *(const float4*)(kvb + r * DD + c);
        *(float4*)&qs[r][c]  = *(const float4*)(qbase + (size_t)(n0 + r) * QKVC + c);
    }
    if (tid < 64) kss[tid] = ksum[bh * DD + tid];
    __syncthreads();

    const int r = tid >> 2;
    const int e0 = (tid & 3) * 16;

    float acc[16];
    #pragma unroll
    for (int j = 0; j < 16; j++) acc[j] = 0.f;
    float zden = 0.f;

    #pragma unroll
    for (int d = 0; d < 64; d++) {
        float qd = qs[r][d];
        zden += qd * kss[d];
        #pragma unroll
        for (int j = 0; j < 16; j++)
            acc[j] += qd * kvs[d][e0 + j];
    }
    float z = 1.f / (zden + 1e-6f);

    size_t obase = ((size_t)b * NN + n0 + r) * CC + h * DD + e0;
    __nv_bfloat162* oh = (__nv_bfloat162*)(ahi + obase);
    __nv_bfloat162* ol = (__nv_bfloat162*)(alo + obase);
    #pragma unroll
    for (int j = 0; j < 16; j += 2) {
        float v0 = acc[j] * z, v1 = acc[j + 1] * z;
        __nv_bfloat16 h0 = __float2bfloat16(v0), h1 = __float2bfloat16(v1);
        __nv_bfloat162 hh; hh.x = h0; hh.y = h1;
        __nv_bfloat162 ll;
        ll.x = __float2bfloat16(v0 - __bfloat162float(h0));
        ll.y = __float2bfloat16(v1 - __bfloat162float(h1));
        oh[j >> 1] = hh; ol[j >> 1] = ll;
    }
}

// ---------------------------------------------------------------------------
extern "C" void kernel_launch(void* const* d_in, const int* in_sizes, int n_in,
                              void* d_out, int out_size)
{
    const float* x     = (const float*)d_in[0];
    const float* Wqkv  = (const float*)d_in[1];
    const float* Wproj = (const float*)d_in[2];
    const float* bproj = (const float*)d_in[3];
    float* out = (float*)d_out;

    float *qkv_p, *kv_p, *ksum_p, *kvp_p, *ksump_p;
    __nv_bfloat16 *xhi, *xlo, *ahi, *alo, *wqh, *wql, *wph, *wpl;
    cudaGetSymbolAddress((void**)&qkv_p, g_qkv);
    cudaGetSymbolAddress((void**)&kv_p,  g_kv);
    cudaGetSymbolAddress((void**)&ksum_p, g_ksum);
    cudaGetSymbolAddress((void**)&kvp_p,  g_kvp);
    cudaGetSymbolAddress((void**)&ksump_p, g_ksump);
    cudaGetSymbolAddress((void**)&xhi, g_xhi);
    cudaGetSymbolAddress((void**)&xlo, g_xlo);
    cudaGetSymbolAddress((void**)&ahi, g_attn_hi);
    cudaGetSymbolAddress((void**)&alo, g_attn_lo);
    cudaGetSymbolAddress((void**)&wqh, g_wqkvT_hi);
    cudaGetSymbolAddress((void**)&wql, g_wqkvT_lo);
    cudaGetSymbolAddress((void**)&wph, g_wprojT_hi);
    cudaGetSymbolAddress((void**)&wpl, g_wprojT_lo);

    cudaFuncSetAttribute(gemm_mma<true, false>,
                         cudaFuncAttributeMaxDynamicSharedMemorySize, GEMM_SMEM);
    cudaFuncSetAttribute(gemm_mma<false, true>,
                         cudaFuncAttributeMaxDynamicSharedMemorySize, GEMM_SMEM);

    // split x into bf16 hi/lo
    {
        size_t n2 = (size_t)MTOT * CC / 2;
        cvt_hilo<<<(unsigned)((n2 + 255) / 256), 256>>>(
            (const float2*)x, (__nv_bfloat162*)xhi, (__nv_bfloat162*)xlo, n2);
    }
    // transpose + split weights to [N][K] bf16 hi/lo
    transpose_cvt<<<dim3(QKVC / 32, KDIM / 32), 256>>>(Wqkv, wqh, wql, KDIM, QKVC);
    transpose_cvt<<<dim3(CC / 32, KDIM / 32), 256>>>(Wproj, wph, wpl, KDIM, CC);

    // GEMM1: qkv = x @ W_qkv  (fused elu+1 on cols < 2048)
    gemm_mma<true, false><<<dim3(QKVC / 128, MTOT / 256), 256, GEMM_SMEM>>>(
        xhi, xlo, wqh, wql, nullptr, qkv_p, QKVC);

    // attention state (8-way N-split, deterministic reduce) + output
    kv_part_kernel<<<BB * HH * KVCHUNK, 256>>>(qkv_p, kvp_p, ksump_p);
    kv_reduce_kernel<<<BB * HH, 256>>>(kvp_p, ksump_p, kv_p, ksum_p);
    qout_kernel<<<dim3(NN / 64, BB * HH), 256>>>(qkv_p, kv_p, ksum_p, ahi, alo);

    // GEMM2: out = attn @ W_proj + b_proj
    gemm_mma<false, true><<<dim3(CC / 128, MTOT / 256), 256, GEMM_SMEM>>>(
        ahi, alo, wph, wpl, bproj, out, CC);
}

// round 7
// speedup vs baseline: 3.3061x; 1.3066x over previous
#include <cuda_runtime.h>
#include <cuda_fp16.h>
#include <math.h>
#include <cstdint>

#define BB 4
#define NN 4096
#define CC 1024
#define HH 16
#define DD 64
#define MTOT (BB*NN)        // 16384
#define QKVC (3*CC)         // 3072
#define KDIM 1024
#define KVCHUNK 8

// ---------------- scratch (device globals; allocation-free) ----------------
__device__ float g_qkv[(size_t)MTOT * QKVC];
__device__ __half g_xh[(size_t)MTOT * CC];
__device__ __half g_attn_h[(size_t)MTOT * CC];
__device__ __half g_wqkvT_hi[(size_t)QKVC * KDIM];
__device__ __half g_wqkvT_lo[(size_t)QKVC * KDIM];
__device__ __half g_wprojT_hi[(size_t)CC * KDIM];
__device__ __half g_wprojT_lo[(size_t)CC * KDIM];
__device__ float g_kvp[KVCHUNK * BB*HH*DD*DD];
__device__ float g_ksump[KVCHUNK * BB*HH*DD];
__device__ float g_kv[BB*HH*DD*DD];
__device__ float g_ksum[BB*HH*DD];

// ---------------- PTX helpers (baseline sm_80-class; assemble on sm_103) ----
__device__ __forceinline__ uint32_t smem_u32(const void* p) {
    uint32_t a;
    asm("{ .reg .u64 t; cvta.to.shared.u64 t, %1; cvt.u32.u64 %0, t; }" : "=r"(a) : "l"(p));
    return a;
}
__device__ __forceinline__ void cp16(uint32_t s, const void* g) {
    asm volatile("cp.async.cg.shared.global [%0], [%1], 16;" :: "r"(s), "l"(g));
}
#define CP_COMMIT() asm volatile("cp.async.commit_group;" ::: "memory")
#define CP_WAIT1()  asm volatile("cp.async.wait_group 1;" ::: "memory")

__device__ __forceinline__ void ldmx4(uint32_t* r, uint32_t addr) {
    asm volatile("ldmatrix.sync.aligned.m8n8.x4.shared.b16 {%0,%1,%2,%3}, [%4];"
                 : "=r"(r[0]), "=r"(r[1]), "=r"(r[2]), "=r"(r[3]) : "r"(addr));
}
__device__ __forceinline__ void mma16816(float* d, const uint32_t* a, const uint32_t* b) {
    asm volatile("mma.sync.aligned.m16n8k16.row.col.f32.f16.f16.f32 "
                 "{%0,%1,%2,%3}, {%4,%5,%6,%7}, {%8,%9}, {%0,%1,%2,%3};"
                 : "+f"(d[0]), "+f"(d[1]), "+f"(d[2]), "+f"(d[3])
                 : "r"(a[0]), "r"(a[1]), "r"(a[2]), "r"(a[3]), "r"(b[0]), "r"(b[1]));
}

// ---------------- converts ----------------
__global__ void cvt_f16(const float2* __restrict__ in, __half2* __restrict__ out, size_t n2) {
    size_t i = (size_t)blockIdx.x * blockDim.x + threadIdx.x;
    if (i >= n2) return;
    float2 v = in[i];
    out[i] = __floats2half2_rn(v.x, v.y);
}

// transpose + split: in [K][N] fp32 -> out hi/lo [N][K] fp16
__global__ __launch_bounds__(256) void transpose_cvt(
    const float* __restrict__ in, __half* __restrict__ hi,
    __half* __restrict__ lo, int K, int N) {
    __shared__ float t[32][33];
    int n0 = blockIdx.x * 32, k0 = blockIdx.y * 32;
    int tx = threadIdx.x & 31, ty = threadIdx.x >> 5;
    #pragma unroll
    for (int i = 0; i < 4; i++)
        t[ty + 8*i][tx] = in[(size_t)(k0 + ty + 8*i) * N + n0 + tx];
    __syncthreads();
    #pragma unroll
    for (int i = 0; i < 4; i++) {
        float v = t[tx][ty + 8*i];
        size_t o = (size_t)(n0 + ty + 8*i) * K + k0 + tx;
        __half h = __float2half_rn(v);
        hi[o] = h;
        lo[o] = __float2half_rn(v - __half2float(h));
    }
}

// ---------------- HMMA fp16 2-term GEMM: C[M,N] = A[M,K] @ (Bh+Bl)[N,K]^T ----
// Block tile 256x128, BK=64, 8 warps (4M x 2N), warp tile 64x64, 3-stage cp.async.
#define KITERS (KDIM / 64)       // 16
#define AHB 32768u               // A: 256 rows x 128B
#define BHB 16384u               // Bh: 128 rows x 128B
#define STAGEB (AHB + 2u*BHB)    // 65536
#define GEMM_SMEM (3 * 65536)    // 196608

template<bool ELU, bool BIAS>
__global__ __launch_bounds__(256, 1) void gemm_mma(
    const __half* __restrict__ A,
    const __half* __restrict__ Bhi, const __half* __restrict__ Blo,
    const float* __restrict__ bias, float* __restrict__ C, int N)
{
    extern __shared__ char sm[];
    const uint32_t sb = smem_u32(sm);
    const int tid = threadIdx.x;
    const int lane = tid & 31, wid = tid >> 5;
    const int wm = (wid >> 1) * 64;      // warp M offset (0,64,128,192)
    const int wn = (wid & 1) * 64;       // warp N offset (0,64)
    const int m0 = blockIdx.y * 256, n0 = blockIdx.x * 128;

    // ---- cp.async geometry: 128B rows, 8 chunks of 16B, 8-way XOR swizzle ----
    const int ch = tid & 7;              // chunk in row
    const int rbase = tid >> 3;          // 0..31
    uint32_t soA[8], soB[4]; size_t gA[8], gB[4];
    #pragma unroll
    for (int i = 0; i < 8; i++) {
        int r = rbase + 32 * i;
        soA[i] = (uint32_t)(r * 128) + (uint32_t)((ch ^ (r & 7)) << 4);
        gA[i] = (size_t)(m0 + r) * KDIM + ch * 8;
    }
    #pragma unroll
    for (int i = 0; i < 4; i++) {
        int r = rbase + 32 * i;
        soB[i] = (uint32_t)(r * 128) + (uint32_t)((ch ^ (r & 7)) << 4);
        gB[i] = (size_t)(n0 + r) * KDIM + ch * 8;
    }

    // ---- ldmatrix geometry ----
    int ra[4], rb[4];
    #pragma unroll
    for (int mt = 0; mt < 4; mt++) ra[mt] = wm + mt * 16 + (lane & 15);
    #pragma unroll
    for (int np = 0; np < 4; np++)
        rb[np] = wn + np * 16 + (lane & 7) + ((lane & 16) ? 8 : 0);
    const int caH = lane >> 4;
    const int cbH = (lane >> 3) & 1;

    float acc[4][8][4];
    #pragma unroll
    for (int mt = 0; mt < 4; mt++)
        #pragma unroll
        for (int nt = 0; nt < 8; nt++)
            #pragma unroll
            for (int j = 0; j < 4; j++) acc[mt][nt][j] = 0.f;

    auto issue = [&](int s) {
        if (s < KITERS) {
            uint32_t st = sb + (uint32_t)(s % 3) * STAGEB;
            size_t ko = (size_t)s * 64;
            #pragma unroll
            for (int i = 0; i < 8; i++)
                cp16(st + soA[i], A + gA[i] + ko);
            #pragma unroll
            for (int i = 0; i < 4; i++) {
                cp16(st + AHB + soB[i],       Bhi + gB[i] + ko);
                cp16(st + AHB + BHB + soB[i], Blo + gB[i] + ko);
            }
        }
        CP_COMMIT();
    };

    issue(0);
    issue(1);

    for (int s = 0; s < KITERS; s++) {
        CP_WAIT1();          // stage s landed (s+1 may be in flight)
        __syncthreads();     // all warps past iteration s-1 -> slot (s+2)%3 free
        issue(s + 2);

        const uint32_t st = sb + (uint32_t)(s % 3) * STAGEB;
        #pragma unroll
        for (int ks = 0; ks < 4; ks++) {
            uint32_t ah[4][4];
            #pragma unroll
            for (int mt = 0; mt < 4; mt++) {
                uint32_t c = (uint32_t)(ks * 2 + caH);
                uint32_t off = (uint32_t)(ra[mt] * 128) + ((c ^ (ra[mt] & 7)) << 4);
                ldmx4(ah[mt], st + off);
            }
            #pragma unroll
            for (int np = 0; np < 4; np++) {
                uint32_t c = (uint32_t)(ks * 2 + cbH);
                uint32_t off = (uint32_t)(rb[np] * 128) + ((c ^ (rb[np] & 7)) << 4);
                uint32_t bh[4], bl[4];
                ldmx4(bh, st + AHB + off);
                ldmx4(bl, st + AHB + BHB + off);
                #pragma unroll
                for (int mt = 0; mt < 4; mt++) {
                    mma16816(acc[mt][2*np  ], ah[mt], bh + 0);
                    mma16816(acc[mt][2*np  ], ah[mt], bl + 0);
                    mma16816(acc[mt][2*np+1], ah[mt], bh + 2);
                    mma16816(acc[mt][2*np+1], ah[mt], bl + 2);
                }
            }
        }
    }

    // ---- epilogue ----
    #pragma unroll
    for (int mt = 0; mt < 4; mt++) {
        #pragma unroll
        for (int nt = 0; nt < 8; nt++) {
            int row = m0 + wm + mt * 16 + (lane >> 2);
            int col = n0 + wn + nt * 8 + (lane & 3) * 2;
            #pragma unroll
            for (int half = 0; half < 2; half++) {
                int r = row + half * 8;
                float v0 = acc[mt][nt][half * 2 + 0];
                float v1 = acc[mt][nt][half * 2 + 1];
                if (ELU) {
                    if (col < 2048)     v0 = (v0 > 0.f) ? (v0 + 1.f) : expf(v0);
                    if (col + 1 < 2048) v1 = (v1 > 0.f) ? (v1 + 1.f) : expf(v1);
                }
                if (BIAS) { v0 += bias[col]; v1 += bias[col + 1]; }
                float2 o; o.x = v0; o.y = v1;
                *(float2*)(C + (size_t)r * N + col) = o;
            }
        }
    }
}

// ---------------- attention: kv partial over N-chunk ----------------
__global__ __launch_bounds__(256) void kv_part_kernel(
    const float* __restrict__ qkv, float* __restrict__ kvp, float* __restrict__ ksump)
{
    const int bx = blockIdx.x;          // 0..511
    const int bh = bx >> 3, chunk = bx & 7;
    const int b = bh >> 4, h = bh & 15;
    const int nbeg = chunk * (NN / KVCHUNK), nend = nbeg + NN / KVCHUNK;
    const float* kbase = qkv + (size_t)b * NN * QKVC + CC + h * DD;
    const float* vbase = qkv + (size_t)b * NN * QKVC + 2 * CC + h * DD;

    __shared__ float ks[32][64];
    __shared__ float vs[32][64];

    const int tid = threadIdx.x;
    const int e0 = (tid & 15) * 4;
    const int d0 = (tid >> 4) * 4;

    float acc[4][4];
    #pragma unroll
    for (int i = 0; i < 4; i++)
        #pragma unroll
        for (int j = 0; j < 4; j++) acc[i][j] = 0.f;
    float ksacc = 0.f;

    for (int n0 = nbeg; n0 < nend; n0 += 32) {
        #pragma unroll
        for (int it = 0; it < 2; it++) {
            int idx = tid + it * 256;
            int r = idx >> 4, cc2 = (idx & 15) * 4;
            *(float4*)&ks[r][cc2] = *(const float4*)(kbase + (size_t)(n0 + r) * QKVC + cc2);
            *(float4*)&vs[r][cc2] = *(const float4*)(vbase + (size_t)(n0 + r) * QKVC + cc2);
        }
        __syncthreads();
        #pragma unroll 8
        for (int nn = 0; nn < 32; nn++) {
            float kd[4], ve[4];
            *(float4*)kd = *(const float4*)&ks[nn][d0];
            *(float4*)ve = *(const float4*)&vs[nn][e0];
            #pragma unroll
            for (int i = 0; i < 4; i++)
                #pragma unroll
                for (int j = 0; j < 4; j++)
                    acc[i][j] += kd[i] * ve[j];
            if (tid < 64) ksacc += ks[nn][tid];
        }
        __syncthreads();
    }
    float* kvo = kvp + (size_t)bx * DD * DD;
    #pragma unroll
    for (int i = 0; i < 4; i++)
        #pragma unroll
        for (int j = 0; j < 4; j++)
            kvo[(d0 + i) * DD + e0 + j] = acc[i][j];
    if (tid < 64) ksump[bx * DD + tid] = ksacc;
}

__global__ __launch_bounds__(256) void kv_reduce_kernel(
    const float* __restrict__ kvp, const float* __restrict__ ksump,
    float* __restrict__ kv, float* __restrict__ ksum)
{
    const int bh = blockIdx.x;
    const int tid = threadIdx.x;
    #pragma unroll
    for (int e = 0; e < 16; e++) {
        int idx = tid + e * 256;
        float s = 0.f;
        #pragma unroll
        for (int c = 0; c < KVCHUNK; c++)
            s += kvp[(size_t)(bh * KVCHUNK + c) * DD * DD + idx];
        kv[(size_t)bh * DD * DD + idx] = s;
    }
    if (tid < DD) {
        float s = 0.f;
        #pragma unroll
        for (int c = 0; c < KVCHUNK; c++)
            s += ksump[(bh * KVCHUNK + c) * DD + tid];
        ksum[bh * DD + tid] = s;
    }
}

// out -> fp16 in [B,N,C] layout (feeds GEMM2 directly)
__global__ __launch_bounds__(256) void qout_kernel(
    const float* __restrict__ qkv, const float* __restrict__ kvmat,
    const float* __restrict__ ksum, __half* __restrict__ ah)
{
    const int bh = blockIdx.y;
    const int b = bh >> 4, h = bh & 15;
    const int n0 = blockIdx.x * 64;

    __shared__ float kvs[64][64];
    __shared__ float qs[64][64];
    __shared__ float kss[64];

    const int tid = threadIdx.x;
    const float* qbase = qkv + (size_t)b * NN * QKVC + h * DD;
    const float* kvb = kvmat + (size_t)bh * DD * DD;

    #pragma unroll
    for (int it = 0; it < 4; it++) {
        int idx = tid + it * 256;
        int r = idx >> 4, c = (idx & 15) * 4;
        *(float4*)&kvs[r][c] = *(const float4*)(kvb + r * DD + c);
        *(float4*)&qs[r][c]  = *(const float4*)(qbase + (size_t)(n0 + r) * QKVC + c);
    }
    if (tid < 64) kss[tid] = ksum[bh * DD + tid];
    __syncthreads();

    const int r = tid >> 2;
    const int e0 = (tid & 3) * 16;

    float acc[16];
    #pragma unroll
    for (int j = 0; j < 16; j++) acc[j] = 0.f;
    float zden = 0.f;

    #pragma unroll
    for (int d = 0; d < 64; d++) {
        float qd = qs[r][d];
        zden += qd * kss[d];
        #pragma unroll
        for (int j = 0; j < 16; j++)
            acc[j] += qd * kvs[d][e0 + j];
    }
    float z = 1.f / (zden + 1e-6f);

    size_t obase = ((size_t)b * NN + n0 + r) * CC + h * DD + e0;
    __half2* oh = (__half2*)(ah + obase);
    #pragma unroll
    for (int j = 0; j < 16; j += 2)
        oh[j >> 1] = __floats2half2_rn(acc[j] * z, acc[j + 1] * z);
}

// ---------------------------------------------------------------------------
extern "C" void kernel_launch(void* const* d_in, const int* in_sizes, int n_in,
                              void* d_out, int out_size)
{
    const float* x     = (const float*)d_in[0];
    const float* Wqkv  = (const float*)d_in[1];
    const float* Wproj = (const float*)d_in[2];
    const float* bproj = (const float*)d_in[3];
    float* out = (float*)d_out;

    float *qkv_p, *kv_p, *ksum_p, *kvp_p, *ksump_p;
    __half *xh, *ah, *wqh, *wql, *wph, *wpl;
    cudaGetSymbolAddress((void**)&qkv_p, g_qkv);
    cudaGetSymbolAddress((void**)&kv_p,  g_kv);
    cudaGetSymbolAddress((void**)&ksum_p, g_ksum);
    cudaGetSymbolAddress((void**)&kvp_p,  g_kvp);
    cudaGetSymbolAddress((void**)&ksump_p, g_ksump);
    cudaGetSymbolAddress((void**)&xh, g_xh);
    cudaGetSymbolAddress((void**)&ah, g_attn_h);
    cudaGetSymbolAddress((void**)&wqh, g_wqkvT_hi);
    cudaGetSymbolAddress((void**)&wql, g_wqkvT_lo);
    cudaGetSymbolAddress((void**)&wph, g_wprojT_hi);
    cudaGetSymbolAddress((void**)&wpl, g_wprojT_lo);

    cudaFuncSetAttribute(gemm_mma<true, false>,
                         cudaFuncAttributeMaxDynamicSharedMemorySize, GEMM_SMEM);
    cudaFuncSetAttribute(gemm_mma<false, true>,
                         cudaFuncAttributeMaxDynamicSharedMemorySize, GEMM_SMEM);

    // x -> fp16
    {
        size_t n2 = (size_t)MTOT * CC / 2;
        cvt_f16<<<(unsigned)((n2 + 255) / 256), 256>>>(
            (const float2*)x, (__half2*)xh, n2);
    }
    // transpose + split weights to [N][K] fp16 hi/lo
    transpose_cvt<<<dim3(QKVC / 32, KDIM / 32), 256>>>(Wqkv, wqh, wql, KDIM, QKVC);
    transpose_cvt<<<dim3(CC / 32, KDIM / 32), 256>>>(Wproj, wph, wpl, KDIM, CC);

    // GEMM1: qkv = x @ W_qkv  (fused elu+1 on cols < 2048)
    gemm_mma<true, false><<<dim3(QKVC / 128, MTOT / 256), 256, GEMM_SMEM>>>(
        xh, wqh, wql, nullptr, qkv_p, QKVC);

    // attention state (8-way N-split, deterministic reduce) + output
    kv_part_kernel<<<BB * HH * KVCHUNK, 256>>>(qkv_p, kvp_p, ksump_p);
    kv_reduce_kernel<<<BB * HH, 256>>>(kvp_p, ksump_p, kv_p, ksum_p);
    qout_kernel<<<dim3(NN / 64, BB * HH), 256>>>(qkv_p, kv_p, ksum_p, ah);

    // GEMM2: out = attn @ W_proj + b_proj
    gemm_mma<false, true><<<dim3(CC / 128, MTOT / 256), 256, GEMM_SMEM>>>(
        ah, wph, wpl, bproj, out, CC);
}